// round 14
// baseline (speedup 1.0000x reference)
#include <cuda_runtime.h>
#include <cuda_fp16.h>
#include <cstdint>

// Problem constants
#define N_POINTS   2097152
#define FEAT_DIM   32
#define W_RES      256   // spatial resolution (x, y, z planes' width)
#define H_RES      128   // temporal resolution (all planes' height)
#define CELLS      (H_RES * W_RES)          // 32768 cells per plane
#define PLANE_ELEMS (CELLS * FEAT_DIM)      // 1,048,576

// Scratch: transposed fp16 planes, layout [H][W][F] (features contiguous).
// 3 * 1M halves = 6 MB static device memory (allowed; allocation is not).
__device__ __half g_planes[3][PLANE_ELEMS];

// ---------------------------------------------------------------------------
// Pre-pass: [F=32, H=128, W=256] f32  ->  [H, W, F] fp16
// Thread per cell (y,x); loops over F with coalesced reads (consecutive
// threads = consecutive x for fixed f). 12 MB read / 6 MB write: ~5 us.
// ---------------------------------------------------------------------------
__global__ void __launch_bounds__(256)
transpose_planes(const float* __restrict__ p0,
                 const float* __restrict__ p1,
                 const float* __restrict__ p2) {
    const int plane = blockIdx.y;
    const float* src = (plane == 0) ? p0 : ((plane == 1) ? p1 : p2);
    const int cell = blockIdx.x * blockDim.x + threadIdx.x;  // 0..32767
    if (cell >= CELLS) return;
    __half2* dst = reinterpret_cast<__half2*>(&g_planes[plane][cell * FEAT_DIM]);
#pragma unroll
    for (int f = 0; f < FEAT_DIM; f += 2) {
        float a = src[(f + 0) * CELLS + cell];
        float b = src[(f + 1) * CELLS + cell];
        dst[f >> 1] = __floats2half2_rn(a, b);
    }
}

// ---------------------------------------------------------------------------
// Main gather kernel.
// 4 threads per point; each thread owns 8 features (16 B fp16 per corner
// -> one LDG.128 per corner; a 4-lane group covers a full 64 B corner).
// 12 LDG.128 per thread total (3 planes x 4 corners).
// ---------------------------------------------------------------------------
__device__ __forceinline__ void acc_corner(float2& a0, float2& a1,
                                           float2& a2, float2& a3,
                                           uint4 v, float w) {
    float2 f;
    f = __half22float2(*reinterpret_cast<__half2*>(&v.x));
    a0.x = fmaf(w, f.x, a0.x); a0.y = fmaf(w, f.y, a0.y);
    f = __half22float2(*reinterpret_cast<__half2*>(&v.y));
    a1.x = fmaf(w, f.x, a1.x); a1.y = fmaf(w, f.y, a1.y);
    f = __half22float2(*reinterpret_cast<__half2*>(&v.z));
    a2.x = fmaf(w, f.x, a2.x); a2.y = fmaf(w, f.y, a2.y);
    f = __half22float2(*reinterpret_cast<__half2*>(&v.w));
    a3.x = fmaf(w, f.x, a3.x); a3.y = fmaf(w, f.y, a3.y);
}

__global__ void __launch_bounds__(256)
kplanes_gather(const float4* __restrict__ inp, float* __restrict__ out) {
    const int gid = blockIdx.x * 256 + threadIdx.x;
    const int pt  = gid >> 2;       // point index
    const int fg  = gid & 3;        // feature group of 8
    const int off = fg * 8;         // feature offset (halves)

    const float4 c = inp[pt];       // 4-way broadcast within lane group

    // temporal coordinate (shared y-axis for all 3 planes), H = 128
    float ty  = fminf(fmaxf((c.w + 1.0f) * 0.5f * 127.0f, 0.0f), 127.0f);
    float y0f = floorf(ty);
    float wy  = ty - y0f;
    int   y0  = (int)y0f;
    int   y1  = min(y0 + 1, 127);
    int   row0 = y0 << 8;           // *W_RES
    int   row1 = y1 << 8;
    float omwy = 1.0f - wy;

    float cx0 = c.x, cx1 = c.y, cx2 = c.z;

    float2 a0 = make_float2(0.f, 0.f);
    float2 a1 = a0, a2 = a0, a3 = a0;

#pragma unroll
    for (int p = 0; p < 3; ++p) {
        float cx = (p == 0) ? cx0 : ((p == 1) ? cx1 : cx2);
        float x   = fminf(fmaxf((cx + 1.0f) * 0.5f * 255.0f, 0.0f), 255.0f);
        float x0f = floorf(x);
        float wx  = x - x0f;
        int   x0  = (int)x0f;
        int   x1  = min(x0 + 1, 255);

        const __half* pl = &g_planes[p][0];
        const uint4* v00p = reinterpret_cast<const uint4*>(pl + ((row0 + x0) * FEAT_DIM + off));
        const uint4* v01p = reinterpret_cast<const uint4*>(pl + ((row0 + x1) * FEAT_DIM + off));
        const uint4* v10p = reinterpret_cast<const uint4*>(pl + ((row1 + x0) * FEAT_DIM + off));
        const uint4* v11p = reinterpret_cast<const uint4*>(pl + ((row1 + x1) * FEAT_DIM + off));
        uint4 v00 = *v00p;
        uint4 v01 = *v01p;
        uint4 v10 = *v10p;
        uint4 v11 = *v11p;

        float omwx = 1.0f - wx;
        float w00 = omwx * omwy;
        float w01 = wx   * omwy;
        float w10 = omwx * wy;
        float w11 = wx   * wy;

        acc_corner(a0, a1, a2, a3, v00, w00);
        acc_corner(a0, a1, a2, a3, v01, w01);
        acc_corner(a0, a1, a2, a3, v10, w10);
        acc_corner(a0, a1, a2, a3, v11, w11);
    }

    float4* o = reinterpret_cast<float4*>(out + pt * FEAT_DIM + off);
    o[0] = make_float4(a0.x, a0.y, a1.x, a1.y);
    o[1] = make_float4(a2.x, a2.y, a3.x, a3.y);
}

// ---------------------------------------------------------------------------
// Launch: transpose pre-pass, then gather. Both on the default stream
// (ordered); graph-capturable (kernel launches only, no alloc/sync).
// Inputs per metadata order: inp, plane0, plane1, plane2.
// ---------------------------------------------------------------------------
extern "C" void kernel_launch(void* const* d_in, const int* in_sizes, int n_in,
                              void* d_out, int out_size) {
    const float4* inp = (const float4*)d_in[0];
    const float*  p0  = (const float*)d_in[1];
    const float*  p1  = (const float*)d_in[2];
    const float*  p2  = (const float*)d_in[3];
    float* out = (float*)d_out;

    dim3 tgrid(CELLS / 256, 3);
    transpose_planes<<<tgrid, 256>>>(p0, p1, p2);

    const int total_threads = N_POINTS * 4;   // 4 threads per point
    kplanes_gather<<<total_threads / 256, 256>>>(inp, out);
}

// round 15
// speedup vs baseline: 1.4244x; 1.4244x over previous
#include <cuda_runtime.h>
#include <cuda_fp16.h>
#include <cstdint>

// Problem constants
#define N_POINTS   2097152
#define FEAT_DIM   32
#define W_RES      256   // spatial resolution (x of each plane)
#define H_RES      128   // temporal resolution (y of each plane)
#define CELLS      (H_RES * W_RES)          // 32768 cells per plane (f32 src)

// Packed fp16 planes, x-pair interleaved, TWO phase copies (even/odd):
//   index = (((plane*2 + parity)*16384) + y*128 + group)*64 + f*2 + side
// One group = 64 halves = 128 B (line-aligned): both x-corners of a pair,
// features interleaved [f0s0, f0s1, f1s0, f1s1, ...].
//   even parity: pair (2g,   2g+1)
//   odd  parity: pair (2g+1, min(2g+2,255))
// 3 planes * 2 parities * 2 MB = 12 MB static scratch.
__device__ __half g_pl[3 * 2 * 16384 * 64];

// ---------------------------------------------------------------------------
// Pre-pass: f32 [F,H,W] -> packed fp16 pair-interleaved layout (both phases).
// Thread = (plane, parity, y, group, feat-quarter): writes one 16 B chunk
// (4 feats x 2 sides). Stores are fully coalesced uint4.
// grid = (512, 2, 3), block = 256.
// ---------------------------------------------------------------------------
__global__ void __launch_bounds__(256)
pack_planes(const float* __restrict__ p0,
            const float* __restrict__ p1,
            const float* __restrict__ p2) {
    const int plane  = blockIdx.z;
    const int parity = blockIdx.y;
    const float* src = (plane == 0) ? p0 : ((plane == 1) ? p1 : p2);

    const int t  = blockIdx.x * 256 + threadIdx.x;   // 0 .. 131071
    const int fq = t & 7;            // feature quarter (4 feats)
    const int g  = (t >> 3) & 127;   // x-pair group
    const int y  = t >> 10;          // 0..127
    const int row = y << 8;          // y * W_RES

    __half2 h2[4];
    if (parity == 0) {
        const int x0 = g << 1;
#pragma unroll
        for (int i = 0; i < 4; ++i) {
            const float* s = src + (fq * 4 + i) * CELLS + row + x0;
            float2 v = *reinterpret_cast<const float2*>(s);   // 8B aligned
            h2[i] = __floats2half2_rn(v.x, v.y);
        }
    } else {
        const int x0 = (g << 1) + 1;
        const int x1 = min(x0 + 1, 255);
#pragma unroll
        for (int i = 0; i < 4; ++i) {
            const float* s = src + (fq * 4 + i) * CELLS + row;
            h2[i] = __floats2half2_rn(s[x0], s[x1]);
        }
    }

    uint4 v;
    v.x = *reinterpret_cast<unsigned*>(&h2[0]);
    v.y = *reinterpret_cast<unsigned*>(&h2[1]);
    v.z = *reinterpret_cast<unsigned*>(&h2[2]);
    v.w = *reinterpret_cast<unsigned*>(&h2[3]);

    const long idx = ((long)((plane * 2 + parity) << 14) + (y << 7) + g) * 64
                   + (fq << 3);
    *reinterpret_cast<uint4*>(g_pl + idx) = v;
}

// ---------------------------------------------------------------------------
// Gather: 8 lanes per point; lane owns 4 features (both x-sides in-register).
// Per lane: 6 LDG.128 (3 planes x 2 t-rows), each warp-instruction touches
// exactly 4 aligned 128B lines (coalescing minimum). One ST.128 per lane.
// ---------------------------------------------------------------------------
__global__ void __launch_bounds__(256)
kplanes_gather(const float4* __restrict__ inp, float* __restrict__ out) {
    const int gid = blockIdx.x * 256 + threadIdx.x;
    const int pt  = gid >> 3;
    const int l8  = gid & 7;
    const int foff = l8 << 3;            // half offset inside a group

    const float4 c = inp[pt];            // 8-way broadcast within lane group

    // temporal coord (shared y for all planes), H = 128
    float ty  = fminf(fmaxf((c.w + 1.0f) * 0.5f * 127.0f, 0.0f), 127.0f);
    float y0f = floorf(ty);
    float wy  = ty - y0f;
    int   y0  = (int)y0f;
    int   y1  = min(y0 + 1, 127);
    const __half2 wy2 = __float2half2_rn(wy);
    const int grow   = y0 << 7;          // group-row offset (groups)
    const int ydelta = (y1 - y0) << 13;  // halves between t-rows

    float acc[4] = {0.f, 0.f, 0.f, 0.f};
    const float cxa[3] = {c.x, c.y, c.z};

#pragma unroll
    for (int p = 0; p < 3; ++p) {
        float x   = fminf(fmaxf((cxa[p] + 1.0f) * 0.5f * 255.0f, 0.0f), 255.0f);
        float x0f = floorf(x);
        float wx  = x - x0f;
        int   x0  = (int)x0f;
        const int parity = x0 & 1;
        const int g      = x0 >> 1;

        const __half* base = g_pl
            + ((long)(((p * 2 + parity) << 14) + grow + g) << 6) + foff;
        uint4 r0 = *reinterpret_cast<const uint4*>(base);
        uint4 r1 = *reinterpret_cast<const uint4*>(base + ydelta);
        const __half2* h0 = reinterpret_cast<const __half2*>(&r0);
        const __half2* h1 = reinterpret_cast<const __half2*>(&r1);

        const float ws1 = wx;
        const float ws0 = 1.0f - wx;

#pragma unroll
        for (int j = 0; j < 4; ++j) {
            // t = f0 + wy*(f1 - f0)  (== omwy*f0 + wy*f1), fp16 pair math
            __half2 d = __hsub2(h1[j], h0[j]);
            __half2 t = __hfma2(wy2, d, h0[j]);
            float2  f = __half22float2(t);          // (side0, side1)
            acc[j] = fmaf(ws0, f.x, acc[j]);
            acc[j] = fmaf(ws1, f.y, acc[j]);
        }
    }

    // lane's feats = [l8*4, l8*4+4) -> one coalesced float4 store
    float4* o = reinterpret_cast<float4*>(out + (pt << 5)) + l8;
    *o = make_float4(acc[0], acc[1], acc[2], acc[3]);
}

// ---------------------------------------------------------------------------
// Launch. Graph-capturable: kernel launches only, default stream ordering.
// Inputs: inp [N,4], plane0/1/2 [32,128,256] f32.
// ---------------------------------------------------------------------------
extern "C" void kernel_launch(void* const* d_in, const int* in_sizes, int n_in,
                              void* d_out, int out_size) {
    const float4* inp = (const float4*)d_in[0];
    const float*  p0  = (const float*)d_in[1];
    const float*  p1  = (const float*)d_in[2];
    const float*  p2  = (const float*)d_in[3];
    float* out = (float*)d_out;

    dim3 pgrid(512, 2, 3);
    pack_planes<<<pgrid, 256>>>(p0, p1, p2);

    const int total_threads = N_POINTS * 8;   // 8 lanes per point
    kplanes_gather<<<total_threads / 256, 256>>>(inp, out);
}

// round 16
// speedup vs baseline: 1.4919x; 1.0474x over previous
#include <cuda_runtime.h>
#include <cuda_fp16.h>
#include <cstdint>

// Problem constants
#define N_POINTS   2097152
#define FEAT_DIM   32
#define W_RES      256
#define H_RES      128
#define CELLS      (H_RES * W_RES)          // 32768 cells per plane (f32 src)

// Packed fp16 planes, x-pair interleaved, TWO phase copies (even/odd):
//   block(plane,parity) = 2MB each; group = 128 B = both x-corners of a pair,
//   features interleaved [f0s0, f0s1, f1s0, f1s1, ...].
//   even parity: pair (2g, 2g+1);  odd: pair (2g+1, min(2g+2,255))
// 12 MB static scratch.
__device__ __half g_pl[3 * 2 * 16384 * 64];

// ---------------------------------------------------------------------------
// Pre-pass: f32 [F,H,W] -> packed fp16 pair-interleaved (both phases).
// ---------------------------------------------------------------------------
__global__ void __launch_bounds__(256)
pack_planes(const float* __restrict__ p0,
            const float* __restrict__ p1,
            const float* __restrict__ p2) {
    const int plane  = blockIdx.z;
    const int parity = blockIdx.y;
    const float* src = (plane == 0) ? p0 : ((plane == 1) ? p1 : p2);

    const int t  = blockIdx.x * 256 + threadIdx.x;   // 0 .. 131071
    const int fq = t & 7;            // feature quarter (4 feats)
    const int g  = (t >> 3) & 127;   // x-pair group
    const int y  = t >> 10;          // 0..127
    const int row = y << 8;

    __half2 h2[4];
    if (parity == 0) {
        const int x0 = g << 1;
#pragma unroll
        for (int i = 0; i < 4; ++i) {
            const float* s = src + (fq * 4 + i) * CELLS + row + x0;
            float2 v = *reinterpret_cast<const float2*>(s);
            h2[i] = __floats2half2_rn(v.x, v.y);
        }
    } else {
        const int x0 = (g << 1) + 1;
        const int x1 = min(x0 + 1, 255);
#pragma unroll
        for (int i = 0; i < 4; ++i) {
            const float* s = src + (fq * 4 + i) * CELLS + row;
            h2[i] = __floats2half2_rn(s[x0], s[x1]);
        }
    }

    uint4 v;
    v.x = *reinterpret_cast<unsigned*>(&h2[0]);
    v.y = *reinterpret_cast<unsigned*>(&h2[1]);
    v.z = *reinterpret_cast<unsigned*>(&h2[2]);
    v.w = *reinterpret_cast<unsigned*>(&h2[3]);

    const unsigned idx = ((unsigned)((plane * 2 + parity) << 14)
                        + (unsigned)(y << 7) + (unsigned)g) * 64u
                        + (unsigned)(fq << 3);
    *reinterpret_cast<uint4*>(g_pl + idx) = v;
}

// ---------------------------------------------------------------------------
// Gather: 8 lanes per point; lane owns 4 features (both x-sides in-register).
// All 6 gather loads issued before interp math (MLP). Interp fully fp16:
//   t   = f0 + wy*(f1-f0)                      (hsub2 + hfma2)
//   acc = hfma2(t, (1-wx, wx), acc)            (x-fold + plane accumulation)
// Final per-feature reduce (low+high) in fp32.
// ---------------------------------------------------------------------------
__device__ __forceinline__ void plane_acc(__half2 (&acc)[4],
                                          const uint4& r0, const uint4& r1,
                                          __half2 wy2, __half2 wx2) {
    const __half2* h0 = reinterpret_cast<const __half2*>(&r0);
    const __half2* h1 = reinterpret_cast<const __half2*>(&r1);
#pragma unroll
    for (int j = 0; j < 4; ++j) {
        __half2 t = __hfma2(wy2, __hsub2(h1[j], h0[j]), h0[j]);
        acc[j] = __hfma2(t, wx2, acc[j]);
    }
}

__global__ void __launch_bounds__(256)
kplanes_gather(const float4* __restrict__ inp, float* __restrict__ out) {
    const int gid = blockIdx.x * 256 + threadIdx.x;
    const int pt  = gid >> 3;
    const int l8  = gid & 7;

    const float4 c = inp[pt];        // 8-way broadcast within lane group

    // temporal coord, H = 128
    float ty  = fminf(fmaxf(fmaf(c.w, 63.5f, 63.5f), 0.0f), 127.0f);
    int   y0  = __float2int_rd(ty);
    float wy  = ty - (float)y0;
    int   y1  = min(y0 + 1, 127);
    const __half2 wy2 = __float2half2_rn(wy);
    const unsigned ybase  = (unsigned)y0 << 14;         // row stride 16 KB
    const unsigned ydelta = (unsigned)(y1 - y0) << 14;
    const unsigned lo     = (unsigned)l8 << 4;

    const float cxa[3] = {c.x, c.y, c.z};
    unsigned off[3];
    __half2  wx2[3];
#pragma unroll
    for (int p = 0; p < 3; ++p) {
        float x  = fminf(fmaxf(fmaf(cxa[p], 127.5f, 127.5f), 0.0f), 255.0f);
        int   x0 = __float2int_rd(x);
        float wx = x - (float)x0;
        wx2[p] = __floats2half2_rn(1.0f - wx, wx);
        off[p] = ((unsigned)(p * 2 + (x0 & 1)) << 21)   // plane/parity block 2MB
               + ybase + ((unsigned)(x0 & ~1) << 6) + lo;
    }

    const char* base = reinterpret_cast<const char*>(g_pl);
    uint4 r00 = *reinterpret_cast<const uint4*>(base + off[0]);
    uint4 r01 = *reinterpret_cast<const uint4*>(base + off[0] + ydelta);
    uint4 r10 = *reinterpret_cast<const uint4*>(base + off[1]);
    uint4 r11 = *reinterpret_cast<const uint4*>(base + off[1] + ydelta);
    uint4 r20 = *reinterpret_cast<const uint4*>(base + off[2]);
    uint4 r21 = *reinterpret_cast<const uint4*>(base + off[2] + ydelta);

    __half2 acc[4];
    const __half2 z = __float2half2_rn(0.0f);
    acc[0] = z; acc[1] = z; acc[2] = z; acc[3] = z;

    plane_acc(acc, r00, r01, wy2, wx2[0]);
    plane_acc(acc, r10, r11, wy2, wx2[1]);
    plane_acc(acc, r20, r21, wy2, wx2[2]);

    float4 o;
    o.x = __low2float(acc[0]) + __high2float(acc[0]);
    o.y = __low2float(acc[1]) + __high2float(acc[1]);
    o.z = __low2float(acc[2]) + __high2float(acc[2]);
    o.w = __low2float(acc[3]) + __high2float(acc[3]);

    reinterpret_cast<float4*>(out + (pt << 5))[l8] = o;
}

// ---------------------------------------------------------------------------
// Launch. Graph-capturable: kernel launches only.
// Inputs: inp [N,4], plane0/1/2 [32,128,256] f32.
// ---------------------------------------------------------------------------
extern "C" void kernel_launch(void* const* d_in, const int* in_sizes, int n_in,
                              void* d_out, int out_size) {
    const float4* inp = (const float4*)d_in[0];
    const float*  p0  = (const float*)d_in[1];
    const float*  p1  = (const float*)d_in[2];
    const float*  p2  = (const float*)d_in[3];
    float* out = (float*)d_out;

    dim3 pgrid(512, 2, 3);
    pack_planes<<<pgrid, 256>>>(p0, p1, p2);

    const int total_threads = N_POINTS * 8;   // 8 lanes per point
    kplanes_gather<<<total_threads / 256, 256>>>(inp, out);
}

// round 17
// speedup vs baseline: 1.5073x; 1.0104x over previous
#include <cuda_runtime.h>
#include <cuda_fp16.h>
#include <cstdint>

// Problem constants
#define N_POINTS   2097152
#define FEAT_DIM   32
#define W_RES      256
#define H_RES      128
#define CELLS      (H_RES * W_RES)          // 32768 cells per plane (f32 src)

// Packed fp16 planes, x-pair interleaved, TWO phase copies (even/odd):
//   block(plane,parity) = 2MB each; group = 128 B = both x-corners of a pair,
//   features interleaved [f0s0, f0s1, f1s0, f1s1, ...].
//   even parity: pair (2g, 2g+1);  odd: pair (2g+1, min(2g+2,255))
// 12 MB static scratch.
__device__ __half g_pl[3 * 2 * 16384 * 64];

// ---------------------------------------------------------------------------
// Pre-pass: f32 [F,H,W] -> packed fp16 pair-interleaved (both phases).
// ---------------------------------------------------------------------------
__global__ void __launch_bounds__(256)
pack_planes(const float* __restrict__ p0,
            const float* __restrict__ p1,
            const float* __restrict__ p2) {
    const int plane  = blockIdx.z;
    const int parity = blockIdx.y;
    const float* src = (plane == 0) ? p0 : ((plane == 1) ? p1 : p2);

    const int t  = blockIdx.x * 256 + threadIdx.x;   // 0 .. 131071
    const int fq = t & 7;            // feature quarter (4 feats)
    const int g  = (t >> 3) & 127;   // x-pair group
    const int y  = t >> 10;          // 0..127
    const int row = y << 8;

    __half2 h2[4];
    if (parity == 0) {
        const int x0 = g << 1;
#pragma unroll
        for (int i = 0; i < 4; ++i) {
            const float* s = src + (fq * 4 + i) * CELLS + row + x0;
            float2 v = *reinterpret_cast<const float2*>(s);
            h2[i] = __floats2half2_rn(v.x, v.y);
        }
    } else {
        const int x0 = (g << 1) + 1;
        const int x1 = min(x0 + 1, 255);
#pragma unroll
        for (int i = 0; i < 4; ++i) {
            const float* s = src + (fq * 4 + i) * CELLS + row;
            h2[i] = __floats2half2_rn(s[x0], s[x1]);
        }
    }

    uint4 v;
    v.x = *reinterpret_cast<unsigned*>(&h2[0]);
    v.y = *reinterpret_cast<unsigned*>(&h2[1]);
    v.z = *reinterpret_cast<unsigned*>(&h2[2]);
    v.w = *reinterpret_cast<unsigned*>(&h2[3]);

    const unsigned idx = ((unsigned)((plane * 2 + parity) << 14)
                        + (unsigned)(y << 7) + (unsigned)g) * 64u
                        + (unsigned)(fq << 3);
    *reinterpret_cast<uint4*>(g_pl + idx) = v;
}

// ---------------------------------------------------------------------------
// Gather: 8 lanes per point; lane owns 4 features (both x-sides in-register).
// All 6 gather loads issued before interp math (MLP). Interp fully fp16:
//   t   = f0 + wy*(f1-f0)                      (hsub2 + hfma2)
//   acc = hfma2(t, (1-wx, wx), acc)            (x-fold + plane accumulation)
// Final per-feature reduce (low+high) in fp32.
// ---------------------------------------------------------------------------
__device__ __forceinline__ void plane_acc(__half2 (&acc)[4],
                                          const uint4& r0, const uint4& r1,
                                          __half2 wy2, __half2 wx2) {
    const __half2* h0 = reinterpret_cast<const __half2*>(&r0);
    const __half2* h1 = reinterpret_cast<const __half2*>(&r1);
#pragma unroll
    for (int j = 0; j < 4; ++j) {
        __half2 t = __hfma2(wy2, __hsub2(h1[j], h0[j]), h0[j]);
        acc[j] = __hfma2(t, wx2, acc[j]);
    }
}

__global__ void __launch_bounds__(256)
kplanes_gather(const float4* __restrict__ inp, float* __restrict__ out) {
    const int gid = blockIdx.x * 256 + threadIdx.x;
    const int pt  = gid >> 3;
    const int l8  = gid & 7;

    const float4 c = inp[pt];        // 8-way broadcast within lane group

    // temporal coord, H = 128
    float ty  = fminf(fmaxf(fmaf(c.w, 63.5f, 63.5f), 0.0f), 127.0f);
    int   y0  = __float2int_rd(ty);
    float wy  = ty - (float)y0;
    int   y1  = min(y0 + 1, 127);
    const __half2 wy2 = __float2half2_rn(wy);
    const unsigned ybase  = (unsigned)y0 << 14;         // row stride 16 KB
    const unsigned ydelta = (unsigned)(y1 - y0) << 14;
    const unsigned lo     = (unsigned)l8 << 4;

    const float cxa[3] = {c.x, c.y, c.z};
    unsigned off[3];
    __half2  wx2[3];
#pragma unroll
    for (int p = 0; p < 3; ++p) {
        float x  = fminf(fmaxf(fmaf(cxa[p], 127.5f, 127.5f), 0.0f), 255.0f);
        int   x0 = __float2int_rd(x);
        float wx = x - (float)x0;
        wx2[p] = __floats2half2_rn(1.0f - wx, wx);
        off[p] = ((unsigned)(p * 2 + (x0 & 1)) << 21)   // plane/parity block 2MB
               + ybase + ((unsigned)(x0 & ~1) << 6) + lo;
    }

    const char* base = reinterpret_cast<const char*>(g_pl);
    uint4 r00 = *reinterpret_cast<const uint4*>(base + off[0]);
    uint4 r01 = *reinterpret_cast<const uint4*>(base + off[0] + ydelta);
    uint4 r10 = *reinterpret_cast<const uint4*>(base + off[1]);
    uint4 r11 = *reinterpret_cast<const uint4*>(base + off[1] + ydelta);
    uint4 r20 = *reinterpret_cast<const uint4*>(base + off[2]);
    uint4 r21 = *reinterpret_cast<const uint4*>(base + off[2] + ydelta);

    __half2 acc[4];
    const __half2 z = __float2half2_rn(0.0f);
    acc[0] = z; acc[1] = z; acc[2] = z; acc[3] = z;

    plane_acc(acc, r00, r01, wy2, wx2[0]);
    plane_acc(acc, r10, r11, wy2, wx2[1]);
    plane_acc(acc, r20, r21, wy2, wx2[2]);

    float4 o;
    o.x = __low2float(acc[0]) + __high2float(acc[0]);
    o.y = __low2float(acc[1]) + __high2float(acc[1]);
    o.z = __low2float(acc[2]) + __high2float(acc[2]);
    o.w = __low2float(acc[3]) + __high2float(acc[3]);

    reinterpret_cast<float4*>(out + (pt << 5))[l8] = o;
}

// ---------------------------------------------------------------------------
// Launch. Graph-capturable: kernel launches only.
// Inputs: inp [N,4], plane0/1/2 [32,128,256] f32.
// ---------------------------------------------------------------------------
extern "C" void kernel_launch(void* const* d_in, const int* in_sizes, int n_in,
                              void* d_out, int out_size) {
    const float4* inp = (const float4*)d_in[0];
    const float*  p0  = (const float*)d_in[1];
    const float*  p1  = (const float*)d_in[2];
    const float*  p2  = (const float*)d_in[3];
    float* out = (float*)d_out;

    dim3 pgrid(512, 2, 3);
    pack_planes<<<pgrid, 256>>>(p0, p1, p2);

    const int total_threads = N_POINTS * 8;   // 8 lanes per point
    kplanes_gather<<<total_threads / 256, 256>>>(inp, out);
}